// round 14
// baseline (speedup 1.0000x reference)
#include <cuda_runtime.h>
#include <math.h>

#define H 2048
#define NE 8
#define THREADS 256                  // 128 tokens per block (2 threads per token)
#define TOK_PER_BLOCK (THREADS / 2)

typedef unsigned long long u64;

__device__ __forceinline__ u64 pk(float a, float b) {
    u64 r; asm("mov.b64 %0, {%1, %2};" : "=l"(r) : "f"(a), "f"(b)); return r;
}
__device__ __forceinline__ u64 fma2(u64 a, u64 b, u64 c) {
    u64 d; asm("fma.rn.f32x2 %0, %1, %2, %3;" : "=l"(d) : "l"(a), "l"(b), "l"(c)); return d;
}
__device__ __forceinline__ float2 upk(u64 v) {
    float2 f; asm("mov.b64 {%0, %1}, %2;" : "=f"(f.x), "=f"(f.y) : "l"(v)); return f;
}
// IEEE round-to-nearest division, immune to --use_fast_math downgrades.
__device__ __forceinline__ float div_rn(float a, float b) {
    float r; asm("div.rn.f32 %0, %1, %2;" : "=f"(r) : "f"(a), "f"(b)); return r;
}

// Weights prepacked as ws4[k][half]: float4 of experts {4h..4h+3} at column k.
extern __shared__ float4 ws4[];      // H * 2 float4 = 64 KB (dynamic)

__global__ void __launch_bounds__(THREADS)
router_kernel(const float* __restrict__ x, const float* __restrict__ w,
              const float* __restrict__ bias, float* __restrict__ out,
              int N, int write_idx)
{
    // Transpose-pack weight matrix into shared memory: ws4[k*2+h] = {w[4h+e][k]}.
    for (int idx = threadIdx.x; idx < H * 2; idx += THREADS) {
        const int k = idx >> 1, h = idx & 1;
        float4 v;
        v.x = w[(4 * h + 0) * H + k];
        v.y = w[(4 * h + 1) * H + k];
        v.z = w[(4 * h + 2) * H + k];
        v.w = w[(4 * h + 3) * H + k];
        ws4[idx] = v;
    }
    __syncthreads();

    const int lt   = threadIdx.x;
    const long long tok = (long long)blockIdx.x * TOK_PER_BLOCK + (lt >> 1);
    const int h    = lt & 1;                      // expert half: 0 -> e0..3, 1 -> e4..7
    const bool valid = (tok < N);
    const long long rtok = valid ? tok : (long long)N - 1;  // clamp for safe reads

    const float4* xrow = (const float4*)(x + rtok * H);     // 512 float4

    // Two sequential FMA chains per thread; f32x2 lanes = experts, so each
    // expert's logit is a single-accumulator chain over k ascending.
    u64 a01 = pk(0.f, 0.f), a23 = pk(0.f, 0.f);

#pragma unroll 4
    for (int kk = 0; kk < H / 4; kk++) {
        const float4 xv = xrow[kk];
        const float xs[4] = {xv.x, xv.y, xv.z, xv.w};
#pragma unroll
        for (int j = 0; j < 4; j++) {
            const float4 wv = ws4[((kk << 2) + j) * 2 + h];  // broadcast LDS.128
            const u64 xd = pk(xs[j], xs[j]);
            a01 = fma2(xd, pk(wv.x, wv.y), a01);
            a23 = fma2(xd, pk(wv.z, wv.w), a23);
        }
    }

    // Exchange halves within the thread pair (lane ^ 1).
    float2 f01 = upk(a01), f23 = upk(a23);
    float myL[4] = {f01.x, f01.y, f23.x, f23.y};
    float oL[4];
#pragma unroll
    for (int i = 0; i < 4; i++)
        oL[i] = __shfl_xor_sync(0xffffffffu, myL[i], 1);

    // Even lane (h==0) of each pair finishes its token.
    if (h == 0 && valid) {
        float L[NE];
#pragma unroll
        for (int i = 0; i < 4; i++) { L[i] = myL[i]; L[4 + i] = oL[i]; }

        float s[NE], sc[NE];
#pragma unroll
        for (int e = 0; e < NE; e++) {
            // Plain sigmoid 1/(1+exp(-x)) — value-validated vs ref (1.2e-6).
            const float t = expf(-L[e]);
            float sg = div_rn(1.0f, 1.0f + t);
            // FTZ to match XLA:GPU: subnormal scores flush to +0.0, which
            // enlarges the zero tie group from L < -88.72 (expf overflow) to
            // L < -87.34 (s < 2^-126). Tie order within the group is the
            // stable ascending-index rank below — matching lax.top_k.
            if (sg < 1.17549435e-38f) sg = 0.0f;
            s[e]  = sg;
            sc[e] = sg + __ldg(&bias[e]);       // bias-corrected selection score
        }

        // Stable descending rank (ties -> lower expert index first),
        // matching jax.lax.top_k over all 8 experts.
        float ssort[NE]; int esort[NE];
#pragma unroll
        for (int e = 0; e < NE; e++) {
            int r = 0;
#pragma unroll
            for (int f = 0; f < NE; f++)
                r += (sc[f] > sc[e]) || ((sc[f] == sc[e]) && (f < e));
            ssort[r] = s[e]; esort[r] = e;
        }

        // Sum gathered (sorted) scores sequentially like the reference's
        // jnp.sum over the top-k axis; then divide, then scale by 1.4.
        float sum = 0.f;
#pragma unroll
        for (int q = 0; q < NE; q++) sum += ssort[q];
        const float d = sum + 1e-10f;

        float* ow = out + tok * NE;
        float* oi = out + (long long)N * NE + tok * NE;
#pragma unroll
        for (int q = 0; q < NE; q++) {
            ow[q] = div_rn(ssort[q], d) * 1.4f;
            if (write_idx) oi[q] = (float)esort[q];
        }
    }
}

extern "C" void kernel_launch(void* const* d_in, const int* in_sizes, int n_in,
                              void* d_out, int out_size)
{
    const float* x    = (const float*)d_in[0];
    const float* w    = (const float*)d_in[1];
    const float* bias = (const float*)d_in[2];
    float* out        = (float*)d_out;

    const int N = in_sizes[0] / H;                 // 4*8192 = 32768 tokens
    const int write_idx = (out_size >= 2 * N * NE) ? 1 : 0;

    const int smem = H * 2 * (int)sizeof(float4);  // 64 KB > 48 KB static cap
    cudaFuncSetAttribute(router_kernel, cudaFuncAttributeMaxDynamicSharedMemorySize, smem);

    const int blocks = (N + TOK_PER_BLOCK - 1) / TOK_PER_BLOCK;
    router_kernel<<<blocks, THREADS, smem>>>(x, w, bias, out, N, write_idx);
}

// round 15
// speedup vs baseline: 1.7064x; 1.7064x over previous
#include <cuda_runtime.h>
#include <math.h>

#define H 2048
#define NE 8
#define TPW 4                      // tokens per warp
#define THREADS 256
#define TOK_PER_BLOCK ((THREADS / 32) * TPW)   // 32 tokens per block

typedef unsigned long long u64;

__device__ __forceinline__ u64 pk(float a, float b) {
    u64 r; asm("mov.b64 %0, {%1, %2};" : "=l"(r) : "f"(a), "f"(b)); return r;
}
__device__ __forceinline__ u64 fma2(u64 a, u64 b, u64 c) {
    u64 d; asm("fma.rn.f32x2 %0, %1, %2, %3;" : "=l"(d) : "l"(a), "l"(b), "l"(c)); return d;
}
__device__ __forceinline__ float2 upk(u64 v) {
    float2 f; asm("mov.b64 {%0, %1}, %2;" : "=f"(f.x), "=f"(f.y) : "l"(v)); return f;
}
// IEEE round-to-nearest division, immune to --use_fast_math downgrades.
__device__ __forceinline__ float div_rn(float a, float b) {
    float r; asm("div.rn.f32 %0, %1, %2;" : "=f"(r) : "f"(a), "f"(b)); return r;
}

extern __shared__ float ws[];  // NE * H floats = 64 KB (dynamic)

__global__ void __launch_bounds__(THREADS, 3)
router_kernel(const float* __restrict__ x, const float* __restrict__ w,
              const float* __restrict__ bias, float* __restrict__ out,
              int N, int write_idx)
{
    // Stage the full 8x2048 fp32 weight matrix into shared memory (64 KB).
    for (int i = threadIdx.x; i < NE * H / 4; i += THREADS)
        ((float4*)ws)[i] = ((const float4*)w)[i];
    __syncthreads();

    const int warp = threadIdx.x >> 5;
    const int lane = threadIdx.x & 31;
    const long long tok0 = (long long)blockIdx.x * TOK_PER_BLOCK + (long long)warp * TPW;
    if (tok0 >= N) return;

    // Clamp row pointers so out-of-range tokens safely re-read the last row.
    const float4* xb[TPW];
#pragma unroll
    for (int t = 0; t < TPW; t++) {
        long long tk = tok0 + t;
        if (tk > (long long)N - 1) tk = (long long)N - 1;
        xb[t] = (const float4*)(x + tk * H);
    }

    u64 acc[TPW][4];               // [token][expert-pair] f32x2 accumulators
#pragma unroll
    for (int t = 0; t < TPW; t++)
#pragma unroll
        for (int p = 0; p < 4; p++) acc[t][p] = pk(0.f, 0.f);

    // Main loop: 16 chunks of 128 columns. Each lane owns 4 consecutive
    // columns -> warp LDG.128 covers 512 contiguous bytes (fully coalesced).
    // Expert loop split into two halves of 4 to keep regs under the
    // 3-CTAs/SM cap (64 KB smem already limits to 3).
    for (int c = 0; c < H; c += 128) {
        const int col = c + lane * 4;

        // Front-batch the 4 independent token loads (MLP >= 4/thread).
        float4 xv[TPW];
#pragma unroll
        for (int t = 0; t < TPW; t++)
            xv[t] = __ldcs(&xb[t][col >> 2]);   // streaming: single-use data

        u64 xlo[TPW], xhi[TPW];
#pragma unroll
        for (int t = 0; t < TPW; t++) {
            xlo[t] = pk(xv[t].x, xv[t].y);
            xhi[t] = pk(xv[t].z, xv[t].w);
        }

#pragma unroll
        for (int half = 0; half < 2; half++) {
            u64 w2[4][2];
#pragma unroll
            for (int e = 0; e < 4; e++) {
                float4 wv = *(const float4*)&ws[(half * 4 + e) * H + col];
                w2[e][0] = pk(wv.x, wv.y);
                w2[e][1] = pk(wv.z, wv.w);
            }
#pragma unroll
            for (int t = 0; t < TPW; t++) {
#pragma unroll
                for (int e = 0; e < 4; e++) {
                    const int p = (half * 4 + e) >> 1;
                    // experts 2j, 2j+1 live in lanes of acc[t][j]:
                    // e even -> contributes to .x, e odd -> .y, but we pack
                    // per-expert chains as pairs: (half*4+e) pairs are
                    // (0,1),(2,3),(4,5),(6,7) -> p index, lane by e&1.
                    // Build the weight operand so lane j of acc gets w[e].
                    (void)p;
                }
                // Direct pairing: experts (4*half+0,4*half+1) -> acc[t][2*half],
                //                 experts (4*half+2,4*half+3) -> acc[t][2*half+1]
                acc[t][2 * half + 0] = fma2(xlo[t], w2[0][0], acc[t][2 * half + 0]);
                acc[t][2 * half + 0] = fma2(xhi[t], w2[0][1], acc[t][2 * half + 0]);
                acc[t][2 * half + 1] = fma2(xlo[t], w2[2][0], acc[t][2 * half + 1]);
                acc[t][2 * half + 1] = fma2(xhi[t], w2[2][1], acc[t][2 * half + 1]);
            }
        }
    }

    // WAIT: the pairing above dropped experts 1,3 per half. Recompute properly
    // is required — see corrected mainloop below. (This block is unreachable;
    // the real kernel uses router_kernel2.)
}

// ---------------------------------------------------------------------------
// Corrected kernel: experts packed two-per-u64 from the start.
// ws2 layout: for pair p (experts 2p, 2p+1), column k: ws2[p * H + k] holds
// {w[2p][k], w[2p+1][k]} as a u64 (f32x2). Lane-consecutive k -> LDS.64
// conflict-free; 4 pairs * H u64 = 64 KB.
// ---------------------------------------------------------------------------
__global__ void __launch_bounds__(THREADS, 3)
router_kernel2(const float* __restrict__ x, const float* __restrict__ w,
               const float* __restrict__ bias, float* __restrict__ out,
               int N, int write_idx)
{
    u64* ws2 = (u64*)ws;

    // Pack weights: ws2[p*H + k] = {w[2p][k], w[2p+1][k]}.
    for (int idx = threadIdx.x; idx < 4 * H; idx += THREADS) {
        const int p = idx >> 11;           // / H
        const int k = idx & (H - 1);       // % H
        ws2[idx] = pk(w[(2 * p) * H + k], w[(2 * p + 1) * H + k]);
    }
    __syncthreads();

    const int warp = threadIdx.x >> 5;
    const int lane = threadIdx.x & 31;
    const long long tok0 = (long long)blockIdx.x * TOK_PER_BLOCK + (long long)warp * TPW;
    if (tok0 >= N) return;

    const float4* xb[TPW];
#pragma unroll
    for (int t = 0; t < TPW; t++) {
        long long tk = tok0 + t;
        if (tk > (long long)N - 1) tk = (long long)N - 1;
        xb[t] = (const float4*)(x + tk * H);
    }

    u64 acc[TPW][4];
#pragma unroll
    for (int t = 0; t < TPW; t++)
#pragma unroll
        for (int p = 0; p < 4; p++) acc[t][p] = pk(0.f, 0.f);

    // 16 chunks of 128 columns; lane owns cols col..col+3 (coalesced 512B/warp).
#pragma unroll 2
    for (int c = 0; c < H; c += 128) {
        const int col = c + lane * 4;

        float4 xv[TPW];
#pragma unroll
        for (int t = 0; t < TPW; t++)
            xv[t] = __ldcs(&xb[t][col >> 2]);   // evict-first: single-use stream

#pragma unroll
        for (int j = 0; j < 4; j++) {           // 4 columns owned by this lane
            u64 wp[4];
#pragma unroll
            for (int p = 0; p < 4; p++)
                wp[p] = ws2[p * H + col + j];    // broadcast-free LDS.64
#pragma unroll
            for (int t = 0; t < TPW; t++) {
                const float xs = (j == 0) ? xv[t].x : (j == 1) ? xv[t].y
                               : (j == 2) ? xv[t].z : xv[t].w;
                const u64 xd = pk(xs, xs);
#pragma unroll
                for (int p = 0; p < 4; p++)
                    acc[t][p] = fma2(xd, wp[p], acc[t][p]);
            }
        }
    }

    // Warp reduce each (token, expert-pair); lane t keeps token t's results.
    float myred[NE];
#pragma unroll
    for (int t = 0; t < TPW; t++) {
#pragma unroll
        for (int p = 0; p < 4; p++) {
            float2 f = upk(acc[t][p]);
            float v0 = f.x, v1 = f.y;
#pragma unroll
            for (int d = 16; d >= 1; d >>= 1) {
                v0 += __shfl_xor_sync(0xffffffffu, v0, d);
                v1 += __shfl_xor_sync(0xffffffffu, v1, d);
            }
            if (lane == t) { myred[2 * p] = v0; myred[2 * p + 1] = v1; }
        }
    }

    // Epilogue (validated in R14): lanes 0..TPW-1 finish one token each.
    if (lane < TPW) {
        const long long tok = tok0 + lane;
        if (tok < N) {
            float s[NE], sc[NE];
#pragma unroll
            for (int e = 0; e < NE; e++) {
                const float t = expf(-myred[e]);
                float sg = div_rn(1.0f, 1.0f + t);
                // FTZ to match XLA:GPU: subnormal scores flush to +0.0.
                if (sg < 1.17549435e-38f) sg = 0.0f;
                s[e]  = sg;
                sc[e] = sg + __ldg(&bias[e]);
            }

            // Stable descending rank (ties -> lower index), = lax.top_k.
            float ssort[NE]; int esort[NE];
#pragma unroll
            for (int e = 0; e < NE; e++) {
                int r = 0;
#pragma unroll
                for (int f = 0; f < NE; f++)
                    r += (sc[f] > sc[e]) || ((sc[f] == sc[e]) && (f < e));
                ssort[r] = s[e]; esort[r] = e;
            }

            float sum = 0.f;
#pragma unroll
            for (int q = 0; q < NE; q++) sum += ssort[q];
            const float d = sum + 1e-10f;

            float* ow = out + tok * NE;
            float* oi = out + (long long)N * NE + tok * NE;
#pragma unroll
            for (int q = 0; q < NE; q++) {
                ow[q] = div_rn(ssort[q], d) * 1.4f;
                if (write_idx) oi[q] = (float)esort[q];
            }
        }
    }
}

extern "C" void kernel_launch(void* const* d_in, const int* in_sizes, int n_in,
                              void* d_out, int out_size)
{
    const float* x    = (const float*)d_in[0];
    const float* w    = (const float*)d_in[1];
    const float* bias = (const float*)d_in[2];
    float* out        = (float*)d_out;

    const int N = in_sizes[0] / H;                 // 4*8192 = 32768 tokens
    const int write_idx = (out_size >= 2 * N * NE) ? 1 : 0;

    const int smem = NE * H * (int)sizeof(float);  // 64 KB > 48 KB static cap
    cudaFuncSetAttribute(router_kernel2, cudaFuncAttributeMaxDynamicSharedMemorySize, smem);

    const int blocks = (N + TOK_PER_BLOCK - 1) / TOK_PER_BLOCK;
    router_kernel2<<<blocks, THREADS, smem>>>(x, w, bias, out, N, write_idx);
}

// round 16
// speedup vs baseline: 1.7094x; 1.0017x over previous
#include <cuda_runtime.h>
#include <math.h>

#define H 2048
#define NE 8
#define TPW 4                      // tokens per warp
#define THREADS 256
#define TOK_PER_BLOCK ((THREADS / 32) * TPW)   // 32 tokens per block

typedef unsigned long long u64;

__device__ __forceinline__ u64 pk(float a, float b) {
    u64 r; asm("mov.b64 %0, {%1, %2};" : "=l"(r) : "f"(a), "f"(b)); return r;
}
__device__ __forceinline__ u64 fma2(u64 a, u64 b, u64 c) {
    u64 d; asm("fma.rn.f32x2 %0, %1, %2, %3;" : "=l"(d) : "l"(a), "l"(b), "l"(c)); return d;
}
__device__ __forceinline__ float2 upk(u64 v) {
    float2 f; asm("mov.b64 {%0, %1}, %2;" : "=f"(f.x), "=f"(f.y) : "l"(v)); return f;
}
// IEEE round-to-nearest division, immune to --use_fast_math downgrades.
__device__ __forceinline__ float div_rn(float a, float b) {
    float r; asm("div.rn.f32 %0, %1, %2;" : "=f"(r) : "f"(a), "f"(b)); return r;
}

extern __shared__ float ws[];  // NE * H floats = 64 KB (dynamic)

__global__ void __launch_bounds__(THREADS, 3)
router_kernel(const float* __restrict__ x, const float* __restrict__ w,
              const float* __restrict__ bias, float* __restrict__ out,
              int N, int write_idx)
{
    // Stage the full 8x2048 fp32 weight matrix into shared memory (64 KB).
    for (int i = threadIdx.x; i < NE * H / 4; i += THREADS)
        ((float4*)ws)[i] = ((const float4*)w)[i];
    __syncthreads();

    const int warp = threadIdx.x >> 5;
    const int lane = threadIdx.x & 31;
    const long long tok0 = (long long)blockIdx.x * TOK_PER_BLOCK + (long long)warp * TPW;
    if (tok0 >= N) return;

    // Clamp row pointers so out-of-range tokens safely re-read the last row.
    const float4* xb[TPW];
#pragma unroll
    for (int t = 0; t < TPW; t++) {
        long long tk = tok0 + t;
        if (tk > (long long)N - 1) tk = (long long)N - 1;
        xb[t] = (const float4*)(x + tk * H);
    }

    u64 acc[TPW][4];               // [token][expert-pair] f32x2 accumulators
#pragma unroll
    for (int t = 0; t < TPW; t++)
#pragma unroll
        for (int p = 0; p < 4; p++) acc[t][p] = pk(0.f, 0.f);

    // Main loop: 16 chunks of 128 columns. Each lane owns 4 consecutive
    // columns -> warp LDG.128 covers 512 contiguous bytes (fully coalesced).
    // Expert loop split into two halves of 4 to keep regs under the
    // 3-CTAs/SM cap (64 KB smem already limits to 3).
    for (int c = 0; c < H; c += 128) {
        const int col = c + lane * 4;

        // Front-batch the 4 independent token loads (MLP >= 4/thread).
        float4 xv[TPW];
#pragma unroll
        for (int t = 0; t < TPW; t++)
            xv[t] = __ldcs(&xb[t][col >> 2]);   // streaming: single-use data

        u64 xlo[TPW], xhi[TPW];
#pragma unroll
        for (int t = 0; t < TPW; t++) {
            xlo[t] = pk(xv[t].x, xv[t].y);
            xhi[t] = pk(xv[t].z, xv[t].w);
        }

#pragma unroll
        for (int half = 0; half < 2; half++) {
            u64 w2[4][2];
#pragma unroll
            for (int e = 0; e < 4; e++) {
                float4 wv = *(const float4*)&ws[(half * 4 + e) * H + col];
                w2[e][0] = pk(wv.x, wv.y);
                w2[e][1] = pk(wv.z, wv.w);
            }
#pragma unroll
            for (int t = 0; t < TPW; t++) {
#pragma unroll
                for (int e = 0; e < 4; e++) {
                    const int p = (half * 4 + e) >> 1;
                    // experts 2j, 2j+1 live in lanes of acc[t][j]:
                    // e even -> contributes to .x, e odd -> .y, but we pack
                    // per-expert chains as pairs: (half*4+e) pairs are
                    // (0,1),(2,3),(4,5),(6,7) -> p index, lane by e&1.
                    // Build the weight operand so lane j of acc gets w[e].
                    (void)p;
                }
                // Direct pairing: experts (4*half+0,4*half+1) -> acc[t][2*half],
                //                 experts (4*half+2,4*half+3) -> acc[t][2*half+1]
                acc[t][2 * half + 0] = fma2(xlo[t], w2[0][0], acc[t][2 * half + 0]);
                acc[t][2 * half + 0] = fma2(xhi[t], w2[0][1], acc[t][2 * half + 0]);
                acc[t][2 * half + 1] = fma2(xlo[t], w2[2][0], acc[t][2 * half + 1]);
                acc[t][2 * half + 1] = fma2(xhi[t], w2[2][1], acc[t][2 * half + 1]);
            }
        }
    }

    // WAIT: the pairing above dropped experts 1,3 per half. Recompute properly
    // is required — see corrected mainloop below. (This block is unreachable;
    // the real kernel uses router_kernel2.)
}

// ---------------------------------------------------------------------------
// Corrected kernel: experts packed two-per-u64 from the start.
// ws2 layout: for pair p (experts 2p, 2p+1), column k: ws2[p * H + k] holds
// {w[2p][k], w[2p+1][k]} as a u64 (f32x2). Lane-consecutive k -> LDS.64
// conflict-free; 4 pairs * H u64 = 64 KB.
// ---------------------------------------------------------------------------
__global__ void __launch_bounds__(THREADS, 3)
router_kernel2(const float* __restrict__ x, const float* __restrict__ w,
               const float* __restrict__ bias, float* __restrict__ out,
               int N, int write_idx)
{
    u64* ws2 = (u64*)ws;

    // Pack weights: ws2[p*H + k] = {w[2p][k], w[2p+1][k]}.
    for (int idx = threadIdx.x; idx < 4 * H; idx += THREADS) {
        const int p = idx >> 11;           // / H
        const int k = idx & (H - 1);       // % H
        ws2[idx] = pk(w[(2 * p) * H + k], w[(2 * p + 1) * H + k]);
    }
    __syncthreads();

    const int warp = threadIdx.x >> 5;
    const int lane = threadIdx.x & 31;
    const long long tok0 = (long long)blockIdx.x * TOK_PER_BLOCK + (long long)warp * TPW;
    if (tok0 >= N) return;

    const float4* xb[TPW];
#pragma unroll
    for (int t = 0; t < TPW; t++) {
        long long tk = tok0 + t;
        if (tk > (long long)N - 1) tk = (long long)N - 1;
        xb[t] = (const float4*)(x + tk * H);
    }

    u64 acc[TPW][4];
#pragma unroll
    for (int t = 0; t < TPW; t++)
#pragma unroll
        for (int p = 0; p < 4; p++) acc[t][p] = pk(0.f, 0.f);

    // 16 chunks of 128 columns; lane owns cols col..col+3 (coalesced 512B/warp).
#pragma unroll 2
    for (int c = 0; c < H; c += 128) {
        const int col = c + lane * 4;

        float4 xv[TPW];
#pragma unroll
        for (int t = 0; t < TPW; t++)
            xv[t] = __ldcs(&xb[t][col >> 2]);   // evict-first: single-use stream

#pragma unroll
        for (int j = 0; j < 4; j++) {           // 4 columns owned by this lane
            u64 wp[4];
#pragma unroll
            for (int p = 0; p < 4; p++)
                wp[p] = ws2[p * H + col + j];    // broadcast-free LDS.64
#pragma unroll
            for (int t = 0; t < TPW; t++) {
                const float xs = (j == 0) ? xv[t].x : (j == 1) ? xv[t].y
                               : (j == 2) ? xv[t].z : xv[t].w;
                const u64 xd = pk(xs, xs);
#pragma unroll
                for (int p = 0; p < 4; p++)
                    acc[t][p] = fma2(xd, wp[p], acc[t][p]);
            }
        }
    }

    // Warp reduce each (token, expert-pair); lane t keeps token t's results.
    float myred[NE];
#pragma unroll
    for (int t = 0; t < TPW; t++) {
#pragma unroll
        for (int p = 0; p < 4; p++) {
            float2 f = upk(acc[t][p]);
            float v0 = f.x, v1 = f.y;
#pragma unroll
            for (int d = 16; d >= 1; d >>= 1) {
                v0 += __shfl_xor_sync(0xffffffffu, v0, d);
                v1 += __shfl_xor_sync(0xffffffffu, v1, d);
            }
            if (lane == t) { myred[2 * p] = v0; myred[2 * p + 1] = v1; }
        }
    }

    // Epilogue (validated in R14): lanes 0..TPW-1 finish one token each.
    if (lane < TPW) {
        const long long tok = tok0 + lane;
        if (tok < N) {
            float s[NE], sc[NE];
#pragma unroll
            for (int e = 0; e < NE; e++) {
                const float t = expf(-myred[e]);
                float sg = div_rn(1.0f, 1.0f + t);
                // FTZ to match XLA:GPU: subnormal scores flush to +0.0.
                if (sg < 1.17549435e-38f) sg = 0.0f;
                s[e]  = sg;
                sc[e] = sg + __ldg(&bias[e]);
            }

            // Stable descending rank (ties -> lower index), = lax.top_k.
            float ssort[NE]; int esort[NE];
#pragma unroll
            for (int e = 0; e < NE; e++) {
                int r = 0;
#pragma unroll
                for (int f = 0; f < NE; f++)
                    r += (sc[f] > sc[e]) || ((sc[f] == sc[e]) && (f < e));
                ssort[r] = s[e]; esort[r] = e;
            }

            float sum = 0.f;
#pragma unroll
            for (int q = 0; q < NE; q++) sum += ssort[q];
            const float d = sum + 1e-10f;

            float* ow = out + tok * NE;
            float* oi = out + (long long)N * NE + tok * NE;
#pragma unroll
            for (int q = 0; q < NE; q++) {
                ow[q] = div_rn(ssort[q], d) * 1.4f;
                if (write_idx) oi[q] = (float)esort[q];
            }
        }
    }
}

extern "C" void kernel_launch(void* const* d_in, const int* in_sizes, int n_in,
                              void* d_out, int out_size)
{
    const float* x    = (const float*)d_in[0];
    const float* w    = (const float*)d_in[1];
    const float* bias = (const float*)d_in[2];
    float* out        = (float*)d_out;

    const int N = in_sizes[0] / H;                 // 4*8192 = 32768 tokens
    const int write_idx = (out_size >= 2 * N * NE) ? 1 : 0;

    const int smem = NE * H * (int)sizeof(float);  // 64 KB > 48 KB static cap
    cudaFuncSetAttribute(router_kernel2, cudaFuncAttributeMaxDynamicSharedMemorySize, smem);

    const int blocks = (N + TOK_PER_BLOCK - 1) / TOK_PER_BLOCK;
    router_kernel2<<<blocks, THREADS, smem>>>(x, w, bias, out, N, write_idx);
}

// round 17
// speedup vs baseline: 1.8422x; 1.0777x over previous
#include <cuda_runtime.h>
#include <math.h>

#define H 2048
#define NE 8
#define TPW 3                      // tokens per warp (fits 3-CTA reg budget w/ prefetch)
#define THREADS 256
#define TOK_PER_BLOCK ((THREADS / 32) * TPW)   // 24 tokens per block
#define NCHUNK (H / 128)                       // 16 chunks of 128 columns

typedef unsigned long long u64;

__device__ __forceinline__ u64 pk(float a, float b) {
    u64 r; asm("mov.b64 %0, {%1, %2};" : "=l"(r) : "f"(a), "f"(b)); return r;
}
__device__ __forceinline__ u64 fma2(u64 a, u64 b, u64 c) {
    u64 d; asm("fma.rn.f32x2 %0, %1, %2, %3;" : "=l"(d) : "l"(a), "l"(b), "l"(c)); return d;
}
__device__ __forceinline__ float2 upk(u64 v) {
    float2 f; asm("mov.b64 {%0, %1}, %2;" : "=f"(f.x), "=f"(f.y) : "l"(v)); return f;
}
// IEEE round-to-nearest division, immune to --use_fast_math downgrades.
__device__ __forceinline__ float div_rn(float a, float b) {
    float r; asm("div.rn.f32 %0, %1, %2;" : "=f"(r) : "f"(a), "f"(b)); return r;
}

extern __shared__ float ws[];  // 64 KB dynamic: 4 expert-pair tables of H u64

// ws2 layout: pair p (experts 2p, 2p+1), column k -> ws2[p*H + k] = {w[2p][k], w[2p+1][k]}.
__global__ void __launch_bounds__(THREADS, 3)
router_kernel(const float* __restrict__ x, const float* __restrict__ w,
              const float* __restrict__ bias, float* __restrict__ out,
              int N, int write_idx)
{
    u64* ws2 = (u64*)ws;

    for (int idx = threadIdx.x; idx < 4 * H; idx += THREADS) {
        const int p = idx >> 11;           // / H
        const int k = idx & (H - 1);       // % H
        ws2[idx] = pk(w[(2 * p) * H + k], w[(2 * p + 1) * H + k]);
    }
    __syncthreads();

    const int warp = threadIdx.x >> 5;
    const int lane = threadIdx.x & 31;
    const long long tok0 = (long long)blockIdx.x * TOK_PER_BLOCK + (long long)warp * TPW;
    if (tok0 >= N) return;

    // Clamped row pointers (out-of-range tokens re-read the last row safely).
    const float4* xb[TPW];
#pragma unroll
    for (int t = 0; t < TPW; t++) {
        long long tk = tok0 + t;
        if (tk > (long long)N - 1) tk = (long long)N - 1;
        xb[t] = (const float4*)(x + tk * H);
    }

    u64 acc[TPW][4];
#pragma unroll
    for (int t = 0; t < TPW; t++)
#pragma unroll
        for (int p = 0; p < 4; p++) acc[t][p] = pk(0.f, 0.f);

    // Software-pipelined mainloop: chunk ci covers columns [ci*128, ci*128+128).
    // Lane owns 4 consecutive columns -> warp LDG.128 = 512B contiguous.
    // Next chunk's 3 x-loads are issued BEFORE computing the current chunk,
    // giving each DRAM load a full chunk of compute latency to resolve.
    float4 xv[2][TPW];
#pragma unroll
    for (int t = 0; t < TPW; t++)
        xv[0][t] = __ldcs(&xb[t][lane]);           // chunk 0: float4 index = lane

    for (int ci = 0; ci < NCHUNK; ci++) {
        const int cur = ci & 1, nxt = cur ^ 1;
        if (ci + 1 < NCHUNK) {
#pragma unroll
            for (int t = 0; t < TPW; t++)
                xv[nxt][t] = __ldcs(&xb[t][(ci + 1) * 32 + lane]);  // evict-first stream
        }

        const int col = ci * 128 + lane * 4;
        float xs[TPW][4];
#pragma unroll
        for (int t = 0; t < TPW; t++) {
            xs[t][0] = xv[cur][t].x; xs[t][1] = xv[cur][t].y;
            xs[t][2] = xv[cur][t].z; xs[t][3] = xv[cur][t].w;
        }

#pragma unroll
        for (int j = 0; j < 4; j++) {
            u64 wp[4];
#pragma unroll
            for (int p = 0; p < 4; p++)
                wp[p] = ws2[p * H + col + j];       // LDS.64, conflict-free
#pragma unroll
            for (int t = 0; t < TPW; t++) {
                const u64 xd = pk(xs[t][j], xs[t][j]);
#pragma unroll
                for (int p = 0; p < 4; p++)
                    acc[t][p] = fma2(xd, wp[p], acc[t][p]);
            }
        }
    }

    // Warp reduce each (token, expert-pair); lane t keeps token t's results.
    float myred[NE];
#pragma unroll
    for (int t = 0; t < TPW; t++) {
#pragma unroll
        for (int p = 0; p < 4; p++) {
            float2 f = upk(acc[t][p]);
            float v0 = f.x, v1 = f.y;
#pragma unroll
            for (int d = 16; d >= 1; d >>= 1) {
                v0 += __shfl_xor_sync(0xffffffffu, v0, d);
                v1 += __shfl_xor_sync(0xffffffffu, v1, d);
            }
            if (lane == t) { myred[2 * p] = v0; myred[2 * p + 1] = v1; }
        }
    }

    // Epilogue (validated R14/R16): lanes 0..TPW-1 finish one token each.
    if (lane < TPW) {
        const long long tok = tok0 + lane;
        if (tok < N) {
            float s[NE], sc[NE];
#pragma unroll
            for (int e = 0; e < NE; e++) {
                const float t = expf(-myred[e]);
                float sg = div_rn(1.0f, 1.0f + t);
                // FTZ to match XLA:GPU: subnormal scores flush to +0.0.
                if (sg < 1.17549435e-38f) sg = 0.0f;
                s[e]  = sg;
                sc[e] = sg + __ldg(&bias[e]);
            }

            // Stable descending rank (ties -> lower index), = lax.top_k.
            float ssort[NE]; int esort[NE];
#pragma unroll
            for (int e = 0; e < NE; e++) {
                int r = 0;
#pragma unroll
                for (int f = 0; f < NE; f++)
                    r += (sc[f] > sc[e]) || ((sc[f] == sc[e]) && (f < e));
                ssort[r] = s[e]; esort[r] = e;
            }

            float sum = 0.f;
#pragma unroll
            for (int q = 0; q < NE; q++) sum += ssort[q];
            const float d = sum + 1e-10f;

            float* ow = out + tok * NE;
            float* oi = out + (long long)N * NE + tok * NE;
#pragma unroll
            for (int q = 0; q < NE; q++) {
                ow[q] = div_rn(ssort[q], d) * 1.4f;
                if (write_idx) oi[q] = (float)esort[q];
            }
        }
    }
}

extern "C" void kernel_launch(void* const* d_in, const int* in_sizes, int n_in,
                              void* d_out, int out_size)
{
    const float* x    = (const float*)d_in[0];
    const float* w    = (const float*)d_in[1];
    const float* bias = (const float*)d_in[2];
    float* out        = (float*)d_out;

    const int N = in_sizes[0] / H;                 // 4*8192 = 32768 tokens
    const int write_idx = (out_size >= 2 * N * NE) ? 1 : 0;

    const int smem = NE * H * (int)sizeof(float);  // 64 KB > 48 KB static cap
    cudaFuncSetAttribute(router_kernel, cudaFuncAttributeMaxDynamicSharedMemorySize, smem);

    const int blocks = (N + TOK_PER_BLOCK - 1) / TOK_PER_BLOCK;
    router_kernel<<<blocks, THREADS, smem>>>(x, w, bias, out, N, write_idx);
}